// round 7
// baseline (speedup 1.0000x reference)
#include <cuda_runtime.h>
#include <cuda_bf16.h>
#include <cstdint>

#define T_STEPS 100

// ------------- device scratch (static; no allocations allowed) -------------
__device__ __align__(16) float2        g_basal2[T_STEPS * 256]; // {0.5*bm, 1.5*bm - bias}
__device__ __align__(16) float         g_q0[256];
__device__ __align__(16) __nv_bfloat16 g_W1T[256 * 256];        // [n][k] = Wapical[k][n]
__device__ __align__(16) __nv_bfloat16 g_W2T[256 * 256];        // [n][k] = Wca1ec5[k][n]

// ------------------------------ helpers ------------------------------------
__device__ __forceinline__ uint32_t smem_u32(const void* p) {
    uint32_t a;
    asm("{ .reg .u64 t; cvta.to.shared.u64 t, %1; cvt.u32.u64 %0, t; }" : "=r"(a) : "l"(p));
    return a;
}
__device__ __forceinline__ float fast_tanh(float x) {
    float y; asm("tanh.approx.f32 %0, %1;" : "=f"(y) : "f"(x)); return y;
}
__device__ __forceinline__ uint32_t bf2(float lo, float hi) {
    uint32_t r;
    asm("cvt.rn.bf16x2.f32 %0, %1, %2;" : "=r"(r) : "f"(hi), "f"(lo));
    return r;
}
#define CSYNC() do { \
    asm volatile("barrier.cluster.arrive.aligned;" ::: "memory"); \
    asm volatile("barrier.cluster.wait.aligned;" ::: "memory"); } while (0)

#define MBAR_INIT(addr, cnt) \
    asm volatile("mbarrier.init.shared.b64 [%0], %1;" :: "r"(addr), "r"((uint32_t)(cnt)) : "memory")

__device__ __forceinline__ void mbar_arrive_local(uint32_t a) {
    asm volatile("mbarrier.arrive.shared.b64 _, [%0];" :: "r"(a) : "memory");
}
__device__ __forceinline__ void mbar_arrive_remote(uint32_t a) {
    asm volatile("mbarrier.arrive.release.cluster.shared::cluster.b64 _, [%0];"
                 :: "r"(a) : "memory");
}
__device__ __forceinline__ void mbar_waitc(uint32_t mbar, uint32_t parity) {
    asm volatile(
        "{\n\t.reg .pred P;\n\t"
        "WL%=:\n\t"
        "mbarrier.try_wait.parity.acquire.cluster.shared::cta.b64 P, [%0], %1, 0x989680;\n\t"
        "@P bra.uni WD%=;\n\t"
        "bra.uni WL%=;\n\t"
        "WD%=:\n\t}"
        :: "r"(mbar), "r"(parity) : "memory");
}

#define LDSM4(R, addr) \
    asm volatile("ldmatrix.sync.aligned.m8n8.x4.shared.b16 {%0,%1,%2,%3}, [%4];" \
        : "=r"((R)[0]), "=r"((R)[1]), "=r"((R)[2]), "=r"((R)[3]) : "r"(addr))

#define MMA16816(D, A0, A1, A2, A3, B0, B1) \
    asm volatile("mma.sync.aligned.m16n8k16.row.col.f32.bf16.bf16.f32 " \
        "{%0,%1,%2,%3}, {%4,%5,%6,%7}, {%8,%9}, {%0,%1,%2,%3};" \
        : "+f"((D)[0]), "+f"((D)[1]), "+f"((D)[2]), "+f"((D)[3]) \
        : "r"(A0), "r"(A1), "r"(A2), "r"(A3), "r"(B0), "r"(B1))

// SW128 blocked layout for [128 rows x 256 bf16 cols]
__device__ __forceinline__ uint32_t tile_off(int row, int col) {
    uint32_t b = (uint32_t)((((row >> 3) + (col >> 6) * 16) << 10) +
                            ((row & 7) << 7) + ((col & 63) << 1));
    return b ^ ((b >> 3) & 0x70);
}

// ------------------------------ prep kernels -------------------------------
__global__ void prep_basal(const float* __restrict__ Wb, const float* __restrict__ bias) {
    __shared__ float ca3[256];
    int t = blockIdx.x, c = threadIdx.x;
    float x = (float)(t + 1);
    float d = x - (float)c * (100.0f / 255.0f);
    ca3[c] = expf(-d * d * (1.0f / 50.0f));
    __syncthreads();
    float s = 0.f;
    for (int j = 0; j < 256; j++) s = fmaf(ca3[j], Wb[j * 256 + c], s);
    g_basal2[t * 256 + c] = make_float2(0.5f * s, fmaf(1.5f, s, -bias[c]));
}

__global__ void prep_w(const float* __restrict__ W1, const float* __restrict__ W2) {
    int n = blockIdx.x & 255, k = threadIdx.x;
    if (blockIdx.x < 256) g_W1T[n * 256 + k] = __float2bfloat16(W1[k * 256 + n]);
    else                  g_W2T[n * 256 + k] = __float2bfloat16(W2[k * 256 + n]);
}

__global__ void prep_q0(const float* __restrict__ W2) {
    __shared__ float ca10[256];
    int e = threadIdx.x;
    ca10[e] = fmaxf(g_basal2[e].y, 0.f);
    __syncthreads();
    float s = 0.f;
    for (int c = 0; c < 256; c++) s = fmaf(ca10[c], W2[c * 256 + e], s);
    g_q0[e] = s;
}

// ------------------------------- main kernel -------------------------------
#define SM_WA    0
#define SM_RED2  2048
#define SM_MB    3072   // E1, F1, E2, F2 (8B each)
#define SM_A     4096
#define SM_B1    69632
#define SM_B2    135168
#define SM_TOTAL 200704
#define NTHR     512

// one 64-col K block (4 kt), A from smem via ldmatrix (warp tile m16)
__device__ __forceinline__ void gemm_blk_smem(uint32_t abase, uint32_t bbase, float* acc,
                                              int arow, int aoff, int brow, int boff, int kb) {
#pragma unroll
    for (int q = 0; q < 4; q++) {
        const int kt = kb * 4 + q;
        uint32_t a[4], b[4][4];
        LDSM4(a, abase + tile_off(arow, kt * 16 + aoff));
#pragma unroll
        for (int np = 0; np < 4; np++)
            LDSM4(b[np], bbase + tile_off(brow + 16 * np, kt * 16 + boff));
#pragma unroll
        for (int nt = 0; nt < 8; nt++)
            MMA16816(&acc[nt * 4], a[0], a[1], a[2], a[3],
                     b[nt >> 1][(nt & 1) * 2], b[nt >> 1][(nt & 1) * 2 + 1]);
    }
}

// 4 kt with A sourced from packed state registers (D->A fragment identity)
__device__ __forceinline__ void gemm_blk_reg(uint32_t bbase, float* acc, const uint32_t* p,
                                             int brow, int boff, int ko) {
#pragma unroll
    for (int q = 0; q < 4; q++) {
        const int kt = ko + q;
        uint32_t b[4][4];
#pragma unroll
        for (int np = 0; np < 4; np++)
            LDSM4(b[np], bbase + tile_off(brow + 16 * np, kt * 16 + boff));
        const uint32_t* ap = &p[4 * q];
#pragma unroll
        for (int nt = 0; nt < 8; nt++)
            MMA16816(&acc[nt * 4], ap[0], ap[1], ap[2], ap[3],
                     b[nt >> 1][(nt & 1) * 2], b[nt >> 1][(nt & 1) * 2 + 1]);
    }
}

// store 16 packed bf16x2 regs into local + peer A tiles (warp tile 16 rows x 64 cols)
__device__ __forceinline__ void store_tile_p(uint32_t la, uint32_t ra, const uint32_t* p,
                                             int mrow0, int colb, int group, int tid4) {
#pragma unroll
    for (int half = 0; half < 2; half++) {
        int row = mrow0 + group + 8 * half;
#pragma unroll
        for (int nt = 0; nt < 8; nt++) {
            uint32_t v = p[nt * 2 + half];
            uint32_t off = tile_off(row, colb + 8 * nt + 2 * tid4);
            asm volatile("st.shared.b32 [%0], %1;" :: "r"(la + off), "r"(v) : "memory");
            asm volatile("st.shared::cluster.b32 [%0], %1;" :: "r"(ra + off), "r"(v) : "memory");
        }
    }
}

__global__ void __launch_bounds__(NTHR, 1) __cluster_dims__(2, 1, 1)
rnn_main(const float* __restrict__ cue, const float* __restrict__ ec5i,
         const float* __restrict__ Waction, float* __restrict__ out) {
    extern __shared__ char smem[];
    const uint32_t sbase = smem_u32(smem);
    const int tid = threadIdx.x, lane = tid & 31, wid = tid >> 5;
    const int mw = wid >> 1;                 // warp M-eighth (0..7), 16 rows
    const int nh = wid & 1;                  // warp N-half within CTA
    const int group = lane >> 2, tid4 = lane & 3;
    const int rank = blockIdx.x & 1;
    const int gbase = (blockIdx.x >> 1) * 128;
    const int mrow0 = 16 * mw;
    const int colb = rank * 128 + 64 * nh;
    const int arow = mrow0 + (lane & 15), aoff = (lane >> 4) * 8;
    const int brow = 64 * nh + ((lane >> 4) << 3) + (lane & 7);
    const int boff = ((lane >> 3) & 1) << 3;
    const int ko = (rank * 2 + nh) * 4;        // kt base of own reg block
    const int kb_sib = rank * 2 + (nh ^ 1);    // sibling 64-col block
    const int pb0 = (1 - rank) * 2;            // peer blocks pb0, pb0+1

    const uint32_t abase = sbase + SM_A;
    const uint32_t b1base = sbase + SM_B1, b2base = sbase + SM_B2;
    const uint32_t mE1 = sbase + SM_MB, mF1 = mE1 + 8, mE2 = mE1 + 16, mF2 = mE1 + 24;
    uint32_t peerA, pE1, pE2, pF1, pF2;
    asm("mapa.shared::cluster.u32 %0, %1, %2;" : "=r"(peerA) : "r"(abase), "r"(rank ^ 1));
    asm("mapa.shared::cluster.u32 %0, %1, %2;" : "=r"(pE1) : "r"(mE1), "r"(rank ^ 1));
    asm("mapa.shared::cluster.u32 %0, %1, %2;" : "=r"(pF1) : "r"(mF1), "r"(rank ^ 1));
    asm("mapa.shared::cluster.u32 %0, %1, %2;" : "=r"(pE2) : "r"(mE2), "r"(rank ^ 1));
    asm("mapa.shared::cluster.u32 %0, %1, %2;" : "=r"(pF2) : "r"(mF2), "r"(rank ^ 1));

    if (tid == 0) {
        MBAR_INIT(mE1, 32); MBAR_INIT(mF1, 16);
        MBAR_INIT(mE2, 32); MBAR_INIT(mF2, 16);
    }

    // ---- init A tile = cue (full 256 cols, bf16, swizzled), coalesced ----
    {
        const float4* src = (const float4*)(cue + (size_t)gbase * 256);
        for (int idx = tid; idx < 8192; idx += NTHR) {
            int r = idx >> 6, c4 = (idx & 63) * 4;
            float4 v = src[idx];
            uint32_t p0 = bf2(v.x, v.y), p1 = bf2(v.z, v.w);
            asm volatile("st.shared.v2.b32 [%0], {%1,%2};"
                         :: "r"(abase + tile_off(r, c4)), "r"(p0), "r"(p1) : "memory");
        }
    }
    // ---- resident weights (this CTA's 128-row half of W1T/W2T) + Waction ----
    {
        const uint4* w1 = (const uint4*)(g_W1T + (size_t)rank * 128 * 256);
        const uint4* w2 = (const uint4*)(g_W2T + (size_t)rank * 128 * 256);
        for (int idx = tid; idx < 4096; idx += NTHR) {
            int r = idx >> 5, c8 = (idx & 31) * 8;
            *(uint4*)(smem + SM_B1 + tile_off(r, c8)) = w1[idx];
            *(uint4*)(smem + SM_B2 + tile_off(r, c8)) = w2[idx];
        }
        for (int i2 = tid; i2 < 512; i2 += NTHR)
            *(float*)(smem + SM_WA + i2 * 4) = Waction[i2];
    }

    // ---- per-thread state: e5 = clip(ec5i + q0) f32; e3p = cue packed bf16 ----
    float e5[32], d[32];
    uint32_t e3p[16], ca1p[16];
#pragma unroll
    for (int half = 0; half < 2; half++) {
        int row = gbase + mrow0 + group + 8 * half;
#pragma unroll
        for (int nt = 0; nt < 8; nt++) {
            int cg = colb + 8 * nt + 2 * tid4;
            int j = nt * 4 + half * 2;
            float2 v5 = *(const float2*)(ec5i + (size_t)row * 256 + cg);
            float2 q  = *(const float2*)(g_q0 + cg);
            e5[j]     = fminf(fmaxf(v5.x + q.x, 0.f), 1.f);
            e5[j + 1] = fminf(fmaxf(v5.y + q.y, 0.f), 1.f);
            float2 v3 = *(const float2*)(cue + (size_t)row * 256 + cg);
            e3p[nt * 2 + half] = bf2(v3.x, v3.y);
        }
    }
    __syncthreads();
    CSYNC();  // mbars + A tiles ready cluster-wide
    if (lane == 0) mbar_arrive_remote(pF2);  // pre-arm F2 phase 0 (16 arrivals)

    for (int i = 1; i < T_STEPS; i++) {
        const uint32_t par = (uint32_t)(i - 1) & 1u;
        __syncthreads();  // local epi2 stores visible / all local warps synced

        // ---- GEMM1: S = ec3 @ W1 (local K first, peer K after F2) ----
#pragma unroll
        for (int j = 0; j < 32; j++) d[j] = 0.f;
        gemm_blk_reg(b1base, d, e3p, brow, boff, ko);
        gemm_blk_smem(abase, b1base, d, arow, aoff, brow, boff, kb_sib);
        mbar_waitc(mF2, par);
        gemm_blk_smem(abase, b1base, d, arow, aoff, brow, boff, pb0);
        gemm_blk_smem(abase, b1base, d, arow, aoff, brow, boff, pb0 + 1);
        __syncwarp();
        if (lane == 0) { mbar_arrive_local(mE1); mbar_arrive_remote(pE1); }

        if (i < T_STEPS - 1) {
            // ---- epilogue1: ca1 = relu(fma(0.5bm, tanh(S/2), 1.5bm-bias)), pack ----
#pragma unroll
            for (int nt = 0; nt < 8; nt++) {
                float4 bb = *(const float4*)(&g_basal2[i * 256 + colb + 8 * nt + 2 * tid4]);
#pragma unroll
                for (int half = 0; half < 2; half++) {
                    int j = nt * 4 + half * 2;
                    float c0 = fmaxf(fmaf(bb.x, fast_tanh(0.5f * d[j]),     bb.y), 0.f);
                    float c1 = fmaxf(fmaf(bb.z, fast_tanh(0.5f * d[j + 1]), bb.w), 0.f);
                    ca1p[nt * 2 + half] = bf2(c0, c1);
                }
            }
            mbar_waitc(mE1, par);  // both CTAs done reading ec3 tile
            store_tile_p(abase, peerA, ca1p, mrow0, colb, group, tid4);
            __syncwarp();
            if (lane == 0) mbar_arrive_remote(pF1);
            __syncthreads();  // local ca1 stores visible

            // ---- GEMM2: e5 += ca1 @ W2 ----
            gemm_blk_reg(b2base, e5, ca1p, brow, boff, ko);
            gemm_blk_smem(abase, b2base, e5, arow, aoff, brow, boff, kb_sib);
            mbar_waitc(mF1, par);
            gemm_blk_smem(abase, b2base, e5, arow, aoff, brow, boff, pb0);
            gemm_blk_smem(abase, b2base, e5, arow, aoff, brow, boff, pb0 + 1);
            __syncwarp();
            if (lane == 0) { mbar_arrive_local(mE2); mbar_arrive_remote(pE2); }

            // ---- epilogue2: clip e5; e3 *= e5 (f32 math, packed storage) ----
#pragma unroll
            for (int half = 0; half < 2; half++)
#pragma unroll
                for (int nt = 0; nt < 8; nt++) {
                    int j = nt * 4 + half * 2;
                    int j2 = nt * 2 + half;
                    float v0 = fminf(fmaxf(e5[j], 0.f), 1.f);
                    float v1 = fminf(fmaxf(e5[j + 1], 0.f), 1.f);
                    e5[j] = v0; e5[j + 1] = v1;
                    uint32_t ep = e3p[j2];
                    float t0 = __bfloat162float(*(__nv_bfloat16*)&ep);
                    uint32_t hi = ep >> 16;
                    float t1 = __bfloat162float(*(__nv_bfloat16*)&hi);
                    e3p[j2] = bf2(t0 * v0, t1 * v1);
                }
            mbar_waitc(mE2, par);  // both CTAs done reading ca1 tile
            store_tile_p(abase, peerA, e3p, mrow0, colb, group, tid4);
            __syncwarp();
            if (lane == 0) mbar_arrive_remote(pF2);
        } else {
            // ---- final step: ca1_99 -> out = ca1 @ Waction ----
#pragma unroll
            for (int nt = 0; nt < 8; nt++) {
                float4 bb = *(const float4*)(&g_basal2[i * 256 + colb + 8 * nt + 2 * tid4]);
#pragma unroll
                for (int half = 0; half < 2; half++) {
                    int j = nt * 4 + half * 2;
                    d[j]     = fmaxf(fmaf(bb.x, fast_tanh(0.5f * d[j]),     bb.y), 0.f);
                    d[j + 1] = fmaxf(fmaf(bb.z, fast_tanh(0.5f * d[j + 1]), bb.w), 0.f);
                }
            }
            const float* wa = (const float*)(smem + SM_WA);
            float* red1 = (float*)(smem + SM_B2);  // B2 dead in last step
            int ct = tid4 * 2 + nh;
#pragma unroll
            for (int half = 0; half < 2; half++) {
                float p0 = 0.f, p1 = 0.f;
#pragma unroll
                for (int nt = 0; nt < 8; nt++)
#pragma unroll
                    for (int c = 0; c < 2; c++) {
                        int cg = colb + 8 * nt + 2 * tid4 + c;
                        float v = d[nt * 4 + half * 2 + c];
                        p0 = fmaf(v, wa[cg * 2 + 0], p0);
                        p1 = fmaf(v, wa[cg * 2 + 1], p1);
                    }
                int row = mrow0 + group + 8 * half;
                red1[(row * 2 + 0) * 8 + ct] = p0;
                red1[(row * 2 + 1) * 8 + ct] = p1;
            }
            __syncthreads();
            if (tid < 256) {
                int row = tid >> 1, a = tid & 1;
                float s = 0.f;
#pragma unroll
                for (int k = 0; k < 8; k++) s += red1[(row * 2 + a) * 8 + k];
                if (rank == 1) {
                    uint32_t r2;
                    asm("mapa.shared::cluster.u32 %0, %1, %2;"
                        : "=r"(r2) : "r"(sbase + SM_RED2 + (uint32_t)(row * 2 + a) * 4), "r"(0));
                    asm volatile("st.shared::cluster.b32 [%0], %1;" :: "r"(r2), "f"(s) : "memory");
                }
                CSYNC();
                if (rank == 0) {
                    float speer = *(const float*)(smem + SM_RED2 + (row * 2 + a) * 4);
                    out[(size_t)(gbase + row) * 2 + a] = s + speer;
                }
            } else {
                CSYNC();
            }
            CSYNC();  // keep cluster alive until all remote traffic done
        }
    }
}

// ------------------------------ launch glue --------------------------------
extern "C" void kernel_launch(void* const* d_in, const int* in_sizes, int n_in,
                              void* d_out, int out_size) {
    const float* cue  = (const float*)d_in[0];
    const float* ec5i = (const float*)d_in[1];
    const float* W1   = (const float*)d_in[2];  // Wapical
    const float* Wb   = (const float*)d_in[3];  // Wbasal
    const float* W2   = (const float*)d_in[4];  // Wca1ec5
    const float* Wa   = (const float*)d_in[5];  // Waction
    const float* bias = (const float*)d_in[6];  // ca1bias
    float* out = (float*)d_out;

    prep_basal<<<100, 256>>>(Wb, bias);
    prep_w<<<512, 256>>>(W1, W2);
    prep_q0<<<1, 256>>>(W2);

    cudaFuncSetAttribute(rnn_main, cudaFuncAttributeMaxDynamicSharedMemorySize, SM_TOTAL);
    rnn_main<<<512, NTHR, SM_TOTAL>>>(cue, ec5i, Wa, out);
}

// round 9
// speedup vs baseline: 1.5361x; 1.5361x over previous
#include <cuda_runtime.h>
#include <cuda_bf16.h>
#include <cstdint>

#define T_STEPS 100

// ------------- device scratch (static; no allocations allowed) -------------
__device__ __align__(16) float2        g_basal2[T_STEPS * 256]; // {0.5*bm, 1.5*bm - bias}
__device__ __align__(16) float         g_q0[256];
__device__ __align__(16) __nv_bfloat16 g_W1T[256 * 256];        // [n][k] = Wapical[k][n]
__device__ __align__(16) __nv_bfloat16 g_W2T[256 * 256];        // [n][k] = Wca1ec5[k][n]

// ------------------------------ helpers ------------------------------------
__device__ __forceinline__ uint32_t smem_u32(const void* p) {
    uint32_t a;
    asm("{ .reg .u64 t; cvta.to.shared.u64 t, %1; cvt.u32.u64 %0, t; }" : "=r"(a) : "l"(p));
    return a;
}
__device__ __forceinline__ float fast_tanh(float x) {
    float y; asm("tanh.approx.f32 %0, %1;" : "=f"(y) : "f"(x)); return y;
}
__device__ __forceinline__ uint32_t bf2(float lo, float hi) {
    uint32_t r;
    asm("cvt.rn.bf16x2.f32 %0, %1, %2;" : "=r"(r) : "f"(hi), "f"(lo));
    return r;
}
#define CSYNC() do { \
    asm volatile("barrier.cluster.arrive.aligned;" ::: "memory"); \
    asm volatile("barrier.cluster.wait.aligned;" ::: "memory"); } while (0)

#define MBAR_INIT(addr, cnt) \
    asm volatile("mbarrier.init.shared.b64 [%0], %1;" :: "r"(addr), "r"((uint32_t)(cnt)) : "memory")

__device__ __forceinline__ void mbar_arrive_local(uint32_t a) {
    asm volatile("mbarrier.arrive.shared.b64 _, [%0];" :: "r"(a) : "memory");
}
__device__ __forceinline__ void mbar_arrive_remote(uint32_t a) {
    asm volatile("mbarrier.arrive.release.cluster.shared::cluster.b64 _, [%0];"
                 :: "r"(a) : "memory");
}
__device__ __forceinline__ void mbar_arm_tx(uint32_t a, uint32_t bytes) {
    asm volatile("mbarrier.arrive.expect_tx.shared.b64 _, [%0], %1;"
                 :: "r"(a), "r"(bytes) : "memory");
}
__device__ __forceinline__ void mbar_waitc(uint32_t mbar, uint32_t parity) {
    asm volatile(
        "{\n\t.reg .pred P;\n\t"
        "WL%=:\n\t"
        "mbarrier.try_wait.parity.acquire.cluster.shared::cta.b64 P, [%0], %1, 0x989680;\n\t"
        "@P bra.uni WD%=;\n\t"
        "bra.uni WL%=;\n\t"
        "WD%=:\n\t}"
        :: "r"(mbar), "r"(parity) : "memory");
}
// one-shot 32KB DSMEM DMA: local smem -> peer smem, completes on peer's mbarrier
__device__ __forceinline__ void bulk_to_peer(uint32_t dst, uint32_t src, uint32_t bytes,
                                             uint32_t peer_mbar) {
    asm volatile(
        "cp.async.bulk.shared::cluster.shared::cta.mbarrier::complete_tx::bytes "
        "[%0], [%1], %2, [%3];"
        :: "r"(dst), "r"(src), "r"(bytes), "r"(peer_mbar) : "memory");
}
#define FENCE_ASYNC() asm volatile("fence.proxy.async.shared::cta;" ::: "memory")

#define LDSM4(R, addr) \
    asm volatile("ldmatrix.sync.aligned.m8n8.x4.shared.b16 {%0,%1,%2,%3}, [%4];" \
        : "=r"((R)[0]), "=r"((R)[1]), "=r"((R)[2]), "=r"((R)[3]) : "r"(addr))

#define MMA16816(D, A0, A1, A2, A3, B0, B1) \
    asm volatile("mma.sync.aligned.m16n8k16.row.col.f32.bf16.bf16.f32 " \
        "{%0,%1,%2,%3}, {%4,%5,%6,%7}, {%8,%9}, {%0,%1,%2,%3};" \
        : "+f"((D)[0]), "+f"((D)[1]), "+f"((D)[2]), "+f"((D)[3]) \
        : "r"(A0), "r"(A1), "r"(A2), "r"(A3), "r"(B0), "r"(B1))

// SW128 blocked layout for [128 rows x 256 bf16 cols]; 64-col groups are
// contiguous 16KB sub-regions -> a 128-col half is one contiguous 32KB block.
__device__ __forceinline__ uint32_t tile_off(int row, int col) {
    uint32_t b = (uint32_t)((((row >> 3) + (col >> 6) * 16) << 10) +
                            ((row & 7) << 7) + ((col & 63) << 1));
    return b ^ ((b >> 3) & 0x70);
}

// ------------------------------ prep kernels -------------------------------
__global__ void prep_basal(const float* __restrict__ Wb, const float* __restrict__ bias) {
    __shared__ float ca3[256];
    int t = blockIdx.x, c = threadIdx.x;
    float x = (float)(t + 1);
    float d = x - (float)c * (100.0f / 255.0f);
    ca3[c] = expf(-d * d * (1.0f / 50.0f));
    __syncthreads();
    float s = 0.f;
    for (int j = 0; j < 256; j++) s = fmaf(ca3[j], Wb[j * 256 + c], s);
    g_basal2[t * 256 + c] = make_float2(0.5f * s, fmaf(1.5f, s, -bias[c]));
}

__global__ void prep_w(const float* __restrict__ W1, const float* __restrict__ W2) {
    int n = blockIdx.x & 255, k = threadIdx.x;
    if (blockIdx.x < 256) g_W1T[n * 256 + k] = __float2bfloat16(W1[k * 256 + n]);
    else                  g_W2T[n * 256 + k] = __float2bfloat16(W2[k * 256 + n]);
}

__global__ void prep_q0(const float* __restrict__ W2) {
    __shared__ float ca10[256];
    int e = threadIdx.x;
    ca10[e] = fmaxf(g_basal2[e].y, 0.f);
    __syncthreads();
    float s = 0.f;
    for (int c = 0; c < 256; c++) s = fmaf(ca10[c], W2[c * 256 + e], s);
    g_q0[e] = s;
}

// ------------------------------- main kernel -------------------------------
#define SM_WA    0
#define SM_RED2  2048
#define SM_MB    3072   // E1, F1, E2, F2 (8B each)
#define SM_A     4096
#define SM_B1    69632
#define SM_B2    135168
#define SM_TOTAL 200704
#define NTHR     512

// one 64-col K block (4 kt): warp tile m32 x n32
__device__ __forceinline__ void gemm_blk(uint32_t abase, uint32_t bbase, float* acc,
                                         int arow, int aoff, int brow, int boff, int kb) {
#pragma unroll
    for (int q = 0; q < 4; q++) {
        const int kt = kb * 4 + q;
        uint32_t a0[4], a1[4], b[2][4];
        LDSM4(a0, abase + tile_off(arow, kt * 16 + aoff));
        LDSM4(a1, abase + tile_off(arow + 16, kt * 16 + aoff));
        LDSM4(b[0], bbase + tile_off(brow, kt * 16 + boff));
        LDSM4(b[1], bbase + tile_off(brow + 16, kt * 16 + boff));
#pragma unroll
        for (int nt = 0; nt < 4; nt++) {
            MMA16816(&acc[nt * 4], a0[0], a0[1], a0[2], a0[3],
                     b[nt >> 1][(nt & 1) * 2], b[nt >> 1][(nt & 1) * 2 + 1]);
            MMA16816(&acc[16 + nt * 4], a1[0], a1[1], a1[2], a1[3],
                     b[nt >> 1][(nt & 1) * 2], b[nt >> 1][(nt & 1) * 2 + 1]);
        }
    }
}

__global__ void __launch_bounds__(NTHR, 1) __cluster_dims__(2, 1, 1)
rnn_main(const float* __restrict__ cue, const float* __restrict__ ec5i,
         const float* __restrict__ Waction, float* __restrict__ out) {
    extern __shared__ char smem[];
    const uint32_t sbase = smem_u32(smem);
    const int tid = threadIdx.x, lane = tid & 31, wid = tid >> 5;
    const int mq = wid >> 2;                 // M quarter 0..3 (32 rows)
    const int nq = wid & 3;                  // N quarter 0..3 (32 cols)
    const int group = lane >> 2, tid4 = lane & 3;
    const int rank = blockIdx.x & 1;
    const int gbase = (blockIdx.x >> 1) * 128;
    const int mrow0 = 32 * mq;
    const int colq = rank * 128 + 32 * nq;   // global col base of warp tile
    const int arow = mrow0 + (lane & 15), aoff = (lane >> 4) * 8;
    const int brow = 32 * nq + ((lane >> 4) << 3) + (lane & 7);
    const int boff = ((lane >> 3) & 1) << 3;
    const int kbl0 = rank * 2;               // local A 64-col blocks
    const int kbp0 = (1 - rank) * 2;         // peer blocks

    const uint32_t abase = sbase + SM_A;
    const uint32_t b1base = sbase + SM_B1, b2base = sbase + SM_B2;
    const uint32_t mE1 = sbase + SM_MB, mF1 = mE1 + 8, mE2 = mE1 + 16, mF2 = mE1 + 24;
    uint32_t peerA, pE1, pE2, pF1, pF2;
    asm("mapa.shared::cluster.u32 %0, %1, %2;" : "=r"(peerA) : "r"(abase), "r"(rank ^ 1));
    asm("mapa.shared::cluster.u32 %0, %1, %2;" : "=r"(pE1) : "r"(mE1), "r"(rank ^ 1));
    asm("mapa.shared::cluster.u32 %0, %1, %2;" : "=r"(pF1) : "r"(mF1), "r"(rank ^ 1));
    asm("mapa.shared::cluster.u32 %0, %1, %2;" : "=r"(pE2) : "r"(mE2), "r"(rank ^ 1));
    asm("mapa.shared::cluster.u32 %0, %1, %2;" : "=r"(pF2) : "r"(mF2), "r"(rank ^ 1));

    if (tid == 0) {
        MBAR_INIT(mE1, 32); MBAR_INIT(mF1, 1);
        MBAR_INIT(mE2, 32); MBAR_INIT(mF2, 1);
    }

    // ---- init A tile = cue (full 256 cols, bf16, swizzled), coalesced ----
    {
        const float4* src = (const float4*)(cue + (size_t)gbase * 256);
        for (int idx = tid; idx < 8192; idx += NTHR) {
            int r = idx >> 6, c4 = (idx & 63) * 4;
            float4 v = src[idx];
            uint32_t p0 = bf2(v.x, v.y), p1 = bf2(v.z, v.w);
            asm volatile("st.shared.v2.b32 [%0], {%1,%2};"
                         :: "r"(abase + tile_off(r, c4)), "r"(p0), "r"(p1) : "memory");
        }
    }
    // ---- resident weights (this CTA's 128-row half of W1T/W2T) + Waction ----
    {
        const uint4* w1 = (const uint4*)(g_W1T + (size_t)rank * 128 * 256);
        const uint4* w2 = (const uint4*)(g_W2T + (size_t)rank * 128 * 256);
        for (int idx = tid; idx < 4096; idx += NTHR) {
            int r = idx >> 5, c8 = (idx & 31) * 8;
            *(uint4*)(smem + SM_B1 + tile_off(r, c8)) = w1[idx];
            *(uint4*)(smem + SM_B2 + tile_off(r, c8)) = w2[idx];
        }
        for (int i2 = tid; i2 < 512; i2 += NTHR)
            *(float*)(smem + SM_WA + i2 * 4) = Waction[i2];
    }

    // ---- per-thread state: e5 = clip(ec5i + q0) f32; e3p = cue packed bf16 ----
    float e5[32], d[32];
    uint32_t e3p[16];
#pragma unroll
    for (int mt = 0; mt < 2; mt++)
#pragma unroll
        for (int half = 0; half < 2; half++) {
            int row = gbase + mrow0 + 16 * mt + group + 8 * half;
#pragma unroll
            for (int nt = 0; nt < 4; nt++) {
                int cg = colq + 8 * nt + 2 * tid4;
                int j = mt * 16 + nt * 4 + half * 2;
                float2 v5 = *(const float2*)(ec5i + (size_t)row * 256 + cg);
                float2 q  = *(const float2*)(g_q0 + cg);
                e5[j]     = fminf(fmaxf(v5.x + q.x, 0.f), 1.f);
                e5[j + 1] = fminf(fmaxf(v5.y + q.y, 0.f), 1.f);
                float2 v3 = *(const float2*)(cue + (size_t)row * 256 + cg);
                e3p[mt * 8 + nt * 2 + half] = bf2(v3.x, v3.y);
            }
        }
    __syncthreads();
    CSYNC();  // mbars + A tiles visible cluster-wide
    if (tid == 0) {
        mbar_arrive_local(mF2);       // phase 0 of F2 completes empty (A = cue everywhere)
        mbar_arm_tx(mF1, 32768);      // phase 0 of F1 = step-1 ca1 copy
    }

    const uint32_t myblk = (uint32_t)rank * 32768u;  // my column half inside A tile

    for (int i = 1; i < T_STEPS; i++) {
        const uint32_t par = (uint32_t)(i - 1) & 1u;

        // ---- GEMM1: S = ec3 @ W1 ----
#pragma unroll
        for (int j = 0; j < 32; j++) d[j] = 0.f;
        gemm_blk(abase, b1base, d, arow, aoff, brow, boff, kbl0);
        gemm_blk(abase, b1base, d, arow, aoff, brow, boff, kbl0 + 1);
        mbar_waitc(mF2, par);                    // peer's e3 half arrived
        if (tid == 0) mbar_arm_tx(mF2, 32768);   // re-arm for next phase
        gemm_blk(abase, b1base, d, arow, aoff, brow, boff, kbp0);
        gemm_blk(abase, b1base, d, arow, aoff, brow, boff, kbp0 + 1);
        __syncwarp();
        if (lane == 0) { mbar_arrive_local(mE1); mbar_arrive_remote(pE1); }

        if (i < T_STEPS - 1) {
            // ---- epilogue1: ca1 = relu(fma(0.5bm, tanh(S/2), 1.5bm-bias)) in d ----
#pragma unroll
            for (int nt = 0; nt < 4; nt++) {
                float4 bb = *(const float4*)(&g_basal2[i * 256 + colq + 8 * nt + 2 * tid4]);
#pragma unroll
                for (int mt = 0; mt < 2; mt++)
#pragma unroll
                    for (int half = 0; half < 2; half++) {
                        int j = mt * 16 + nt * 4 + half * 2;
                        d[j]     = fmaxf(fmaf(bb.x, fast_tanh(0.5f * d[j]),     bb.y), 0.f);
                        d[j + 1] = fmaxf(fmaf(bb.z, fast_tanh(0.5f * d[j + 1]), bb.w), 0.f);
                    }
            }
            __syncthreads();  // all local warps done reading A (GEMM1 complete locally)
            // store ca1 into my column half (local only)
#pragma unroll
            for (int mt = 0; mt < 2; mt++)
#pragma unroll
                for (int half = 0; half < 2; half++) {
                    int row = mrow0 + 16 * mt + group + 8 * half;
#pragma unroll
                    for (int nt = 0; nt < 4; nt++) {
                        int j = mt * 16 + nt * 4 + half * 2;
                        uint32_t p = bf2(d[j], d[j + 1]);
                        asm volatile("st.shared.b32 [%0], %1;"
                            :: "r"(abase + tile_off(row, colq + 8 * nt + 2 * tid4)), "r"(p)
                            : "memory");
                    }
                }
            __syncthreads();  // ca1 half visible locally
            if (tid == 0) {
                FENCE_ASYNC();
                mbar_waitc(mE1, par);  // peer done reading its A (safe to overwrite peer region)
                bulk_to_peer(peerA + myblk, abase + myblk, 32768, pF1);
            }

            // ---- GEMM2: e5 += ca1 @ W2 ----
            gemm_blk(abase, b2base, e5, arow, aoff, brow, boff, kbl0);
            gemm_blk(abase, b2base, e5, arow, aoff, brow, boff, kbl0 + 1);
            mbar_waitc(mF1, par);
            if (tid == 0) mbar_arm_tx(mF1, 32768);
            gemm_blk(abase, b2base, e5, arow, aoff, brow, boff, kbp0);
            gemm_blk(abase, b2base, e5, arow, aoff, brow, boff, kbp0 + 1);
            __syncwarp();
            if (lane == 0) { mbar_arrive_local(mE2); mbar_arrive_remote(pE2); }

            // ---- epilogue2: clip e5; e3 *= e5 (f32 math, packed bf16 storage) ----
#pragma unroll
            for (int mt = 0; mt < 2; mt++)
#pragma unroll
                for (int half = 0; half < 2; half++)
#pragma unroll
                    for (int nt = 0; nt < 4; nt++) {
                        int j = mt * 16 + nt * 4 + half * 2;
                        int j2 = mt * 8 + nt * 2 + half;
                        float v0 = fminf(fmaxf(e5[j], 0.f), 1.f);
                        float v1 = fminf(fmaxf(e5[j + 1], 0.f), 1.f);
                        e5[j] = v0; e5[j + 1] = v1;
                        uint32_t ep = e3p[j2];
                        float t0 = __bfloat162float(*(__nv_bfloat16*)&ep);
                        uint32_t hi = ep >> 16;
                        float t1 = __bfloat162float(*(__nv_bfloat16*)&hi);
                        e3p[j2] = bf2(t0 * v0, t1 * v1);
                    }
            __syncthreads();  // all local warps done reading A (GEMM2 complete locally)
#pragma unroll
            for (int mt = 0; mt < 2; mt++)
#pragma unroll
                for (int half = 0; half < 2; half++) {
                    int row = mrow0 + 16 * mt + group + 8 * half;
#pragma unroll
                    for (int nt = 0; nt < 4; nt++) {
                        uint32_t p = e3p[mt * 8 + nt * 2 + half];
                        asm volatile("st.shared.b32 [%0], %1;"
                            :: "r"(abase + tile_off(row, colq + 8 * nt + 2 * tid4)), "r"(p)
                            : "memory");
                    }
                }
            __syncthreads();  // e3 half visible locally (next GEMM1 local blocks)
            if (tid == 0) {
                FENCE_ASYNC();
                mbar_waitc(mE2, par);  // peer done reading ca1 region
                bulk_to_peer(peerA + myblk, abase + myblk, 32768, pF2);
            }
        } else {
            // ---- final step: ca1_99 -> out = ca1 @ Waction ----
#pragma unroll
            for (int nt = 0; nt < 4; nt++) {
                float4 bb = *(const float4*)(&g_basal2[i * 256 + colq + 8 * nt + 2 * tid4]);
#pragma unroll
                for (int mt = 0; mt < 2; mt++)
#pragma unroll
                    for (int half = 0; half < 2; half++) {
                        int j = mt * 16 + nt * 4 + half * 2;
                        d[j]     = fmaxf(fmaf(bb.x, fast_tanh(0.5f * d[j]),     bb.y), 0.f);
                        d[j + 1] = fmaxf(fmaf(bb.z, fast_tanh(0.5f * d[j + 1]), bb.w), 0.f);
                    }
            }
            const float* wa = (const float*)(smem + SM_WA);
            float* red1 = (float*)(smem + SM_B2);  // B2 dead in last step: [128][2][16]
            __syncthreads();                       // all B2 LDSM reads done (step 98)
            int ct = nq * 4 + tid4;
#pragma unroll
            for (int mt = 0; mt < 2; mt++)
#pragma unroll
                for (int half = 0; half < 2; half++) {
                    float p0 = 0.f, p1 = 0.f;
#pragma unroll
                    for (int nt = 0; nt < 4; nt++)
#pragma unroll
                        for (int c = 0; c < 2; c++) {
                            int cg = colq + 8 * nt + 2 * tid4 + c;
                            float v = d[mt * 16 + nt * 4 + half * 2 + c];
                            p0 = fmaf(v, wa[cg * 2 + 0], p0);
                            p1 = fmaf(v, wa[cg * 2 + 1], p1);
                        }
                    int row = mrow0 + 16 * mt + group + 8 * half;
                    red1[(row * 2 + 0) * 16 + ct] = p0;
                    red1[(row * 2 + 1) * 16 + ct] = p1;
                }
            __syncthreads();
            float s = 0.f;
            if (tid < 256) {
                int row = tid >> 1, a = tid & 1;
#pragma unroll
                for (int k = 0; k < 16; k++) s += red1[(row * 2 + a) * 16 + k];
                if (rank == 1) {
                    uint32_t r2;
                    asm("mapa.shared::cluster.u32 %0, %1, %2;"
                        : "=r"(r2) : "r"(sbase + SM_RED2 + (uint32_t)(row * 2 + a) * 4), "r"(0));
                    asm volatile("st.shared::cluster.b32 [%0], %1;" :: "r"(r2), "f"(s) : "memory");
                }
            }
            CSYNC();
            if (tid < 256 && rank == 0) {
                int row = tid >> 1, a = tid & 1;
                float speer = *(const float*)(smem + SM_RED2 + (row * 2 + a) * 4);
                out[(size_t)(gbase + row) * 2 + a] = s + speer;
            }
            CSYNC();  // keep cluster alive until all remote traffic done
        }
    }
}

// ------------------------------ launch glue --------------------------------
extern "C" void kernel_launch(void* const* d_in, const int* in_sizes, int n_in,
                              void* d_out, int out_size) {
    const float* cue  = (const float*)d_in[0];
    const float* ec5i = (const float*)d_in[1];
    const float* W1   = (const float*)d_in[2];  // Wapical
    const float* Wb   = (const float*)d_in[3];  // Wbasal
    const float* W2   = (const float*)d_in[4];  // Wca1ec5
    const float* Wa   = (const float*)d_in[5];  // Waction
    const float* bias = (const float*)d_in[6];  // ca1bias
    float* out = (float*)d_out;

    prep_basal<<<100, 256>>>(Wb, bias);
    prep_w<<<512, 256>>>(W1, W2);
    prep_q0<<<1, 256>>>(W2);

    cudaFuncSetAttribute(rnn_main, cudaFuncAttributeMaxDynamicSharedMemorySize, SM_TOTAL);
    rnn_main<<<512, NTHR, SM_TOTAL>>>(cue, ec5i, Wa, out);
}